// round 6
// baseline (speedup 1.0000x reference)
#include <cuda_runtime.h>

// Input (B,H,W,C) = (16,128,128,128) fp32, factor (2,2) half-pixel bilinear
// upsample -> (16,256,256,128) fp32.
//
// Oct formulation: one thread handles TWO adjacent quads (source cols w0,w0+1
// plus shared right tap w0+2) for one source row pair -> 6 tap loads,
// up to 8 interior outputs (2 rows x 4 cols). Clamped-tap lerps collapse
// exactly (fma form), so edge VALUES need no special math; but the stores to
// output col 256 (j==63, colA+3) and row 256 (qh==127) don't exist and must
// be predicated. Row 0 / col 0 emitted by qh==0 / j==0 threads.

#define B_   16
#define H_   128
#define W_   128
#define C4_  32          // 128 channels / 4
#define OH_  256
#define OW_  256

__device__ __forceinline__ float4 lerp4(float4 v0, float4 v1, float t) {
    float4 r;
    r.x = fmaf(t, v1.x - v0.x, v0.x);
    r.y = fmaf(t, v1.y - v0.y, v0.y);
    r.z = fmaf(t, v1.z - v0.z, v0.z);
    r.w = fmaf(t, v1.w - v0.w, v0.w);
    return r;
}

__global__ __launch_bounds__(256) void upsample2x_oct(
    const float4* __restrict__ in, float4* __restrict__ out)
{
    int idx = blockIdx.x * 256 + threadIdx.x;   // B*128*64*32 threads
    int c4 = idx & (C4_ - 1);
    int j  = (idx >> 5) & 63;          // quad-pair column (64 of them)
    int qh = (idx >> 11) & (H_ - 1);
    int b  = idx >> 18;

    int w0 = 2 * j;
    int w1 = w0 + 1;
    int w2 = w0 + 2 < W_ ? w0 + 2 : W_ - 1;   // clamp only at j==63
    int r1 = qh + 1 < H_ ? qh + 1 : H_ - 1;   // clamp only at qh==127

    bool jr = (j < 63);                        // colA+3 == 256 when j==63

    const float4* base = in + (size_t)b * (H_ * W_ * C4_) + c4;
    const float4* rl = base + qh * (W_ * C4_);
    const float4* rh = base + r1 * (W_ * C4_);
    float4 v00 = __ldg(rl + w0 * C4_);
    float4 v01 = __ldg(rl + w1 * C4_);
    float4 v02 = __ldg(rl + w2 * C4_);
    float4 v10 = __ldg(rh + w0 * C4_);
    float4 v11 = __ldg(rh + w1 * C4_);
    float4 v12 = __ldg(rh + w2 * C4_);

    // H interpolation first (matches reference order), both fracs.
    float4 a0 = lerp4(v00, v10, 0.25f);
    float4 a1 = lerp4(v01, v11, 0.25f);
    float4 a2 = lerp4(v02, v12, 0.25f);
    float4 b0 = lerp4(v00, v10, 0.75f);
    float4 b1 = lerp4(v01, v11, 0.75f);
    float4 b2 = lerp4(v02, v12, 0.75f);

    float4* obase = out + (size_t)b * (OH_ * OW_ * C4_) + c4;
    int rowA = 2 * qh + 1;
    int colA = 4 * j + 1;                       // cols colA..colA+3, last needs jr

    float4* oA = obase + (size_t)rowA * (OW_ * C4_);
    __stcs(oA + (colA    ) * C4_, lerp4(a0, a1, 0.25f));
    __stcs(oA + (colA + 1) * C4_, lerp4(a0, a1, 0.75f));
    __stcs(oA + (colA + 2) * C4_, lerp4(a1, a2, 0.25f));
    if (jr)
        __stcs(oA + (colA + 3) * C4_, lerp4(a1, a2, 0.75f));

    if (qh < H_ - 1) {                          // row 2qh+2 (row 256 doesn't exist)
        float4* oB = oA + OW_ * C4_;
        __stcs(oB + (colA    ) * C4_, lerp4(b0, b1, 0.25f));
        __stcs(oB + (colA + 1) * C4_, lerp4(b0, b1, 0.75f));
        __stcs(oB + (colA + 2) * C4_, lerp4(b1, b2, 0.25f));
        if (jr)
            __stcs(oB + (colA + 3) * C4_, lerp4(b1, b2, 0.75f));
    }

    // Output row 0 = source row 0 (h-frac collapses), w-interp as usual.
    if (qh == 0) {
        __stcs(obase + (colA    ) * C4_, lerp4(v00, v01, 0.25f));
        __stcs(obase + (colA + 1) * C4_, lerp4(v00, v01, 0.75f));
        __stcs(obase + (colA + 2) * C4_, lerp4(v01, v02, 0.25f));
        if (jr)
            __stcs(obase + (colA + 3) * C4_, lerp4(v01, v02, 0.75f));
        if (j == 0)
            __stcs(obase, v00);                 // (0,0) corner
    }

    // Output col 0 = source col 0 (w-frac collapses): values a0 / b0.
    if (j == 0) {
        __stcs(obase + (size_t)rowA * (OW_ * C4_), a0);
        if (qh < H_ - 1)
            __stcs(obase + (size_t)(rowA + 1) * (OW_ * C4_), b0);
    }
}

extern "C" void kernel_launch(void* const* d_in, const int* in_sizes, int n_in,
                              void* d_out, int out_size) {
    const float4* in = (const float4*)d_in[0];
    float4* out = (float4*)d_out;
    int total = B_ * H_ * 64 * C4_;    // 4,194,304 threads
    upsample2x_oct<<<total / 256, 256>>>(in, out);
}